// round 9
// baseline (speedup 1.0000x reference)
#include <cuda_runtime.h>
#include <cuda_bf16.h>
#include <math.h>

#define HW     9216    // 96*96
#define DIM    96
#define NSAMP  8
#define NBLK16 16
#define NSLICE 9
#define NCTA   (NBLK16 * NSLICE)   // 144 CTAs = single wave
#define TPB    1024
#define INFG   3000    // scan INF marker (short-safe)
#define GCLAMP 150     // clamp for s16 phase-2: 150^2+95^2 = 31525 < 32767
#define EMPTYT 22500   // min possible d^2 when target empty (= GCLAMP^2)
#define NRWIN  12      // 1024 pixels span <= 12 rows

__device__ int g_part[NCTA];
__device__ int g_count = 0;

__global__ __launch_bounds__(TPB, 1)
void hausdorff_kernel(const float* __restrict__ predict,
                      const float* __restrict__ target,
                      float* __restrict__ out)
{
    const int bx    = blockIdx.x;
    const int blk16 = bx & 15;
    const int slice = bx >> 4;
    const int s     = blk16 >> 1;
    const int dir   = blk16 & 1;
    const int tid   = threadIdx.x;
    const int lane  = tid & 31;

    __shared__ unsigned char tgm[HW];                       // target mask
    __shared__ short gFs[NRWIN * DIM];                      // fwd scan, window
    __shared__ short gBs[NRWIN * DIM];                      // bwd scan, window
    __shared__ __align__(16) unsigned short hsq16[NRWIN * DIM]; // clamped g^2+jp^2
    __shared__ int   warpmax[32];
    __shared__ int   lastflag;

    const int r0 = (slice * TPB) / DIM;                     // first row this CTA needs

    const float* pbase = predict + s * HW;
    const float* tbase = target  + s * HW;
    const float* tsrc  = dir ? pbase : tbase;

    // ---- build target mask, vectorized ((x > 0.5f) == (rint(x) > 0.5) on [0,1)) ----
    const float4* t4 = (const float4*)tsrc;
    #pragma unroll
    for (int v = 0; v < 3; ++v) {
        int idx = v * TPB + tid;
        if (idx < HW / 4) {
            float4 x = t4[idx];
            uchar4 m;
            m.x = x.x > 0.5f;
            m.y = x.y > 0.5f;
            m.z = x.z > 0.5f;
            m.w = x.w > 0.5f;
            ((uchar4*)tgm)[idx] = m;
        }
    }

    // ---- this thread's source-pixel bit (register, no smem) ----
    const int q0 = slice * TPB + tid;
    const bool abit   = pbase[q0] > 0.5f;
    const bool bbit   = tbase[q0] > 0.5f;
    const bool srcbit = dir ? (bbit && !abit) : (abit && !bbit);
    __syncthreads();

    // ---- phase 1: full-column scans, store ONLY the window rows ----
    if (tid < DIM) {
        const int j = tid;
        int d = INFG;
        #pragma unroll
        for (int i = 0; i < DIM; ++i) {
            d = tgm[i * DIM + j] ? 0 : (d + 1);
            if ((unsigned)(i - r0) < NRWIN)
                gFs[(i - r0) * DIM + j] = (short)d;
        }
    } else if (tid < 2 * DIM) {
        const int j = tid - DIM;
        int d = INFG;
        #pragma unroll
        for (int i = DIM - 1; i >= 0; --i) {
            d = tgm[i * DIM + j] ? 0 : (d + 1);
            if ((unsigned)(i - r0) < NRWIN)
                gBs[(i - r0) * DIM + j] = (short)d;
        }
    }
    __syncthreads();

    // ---- mini-combine: hsq16 = min(g,GCLAMP)^2 + jp^2 (fits s16 range) ----
    {
        int e = tid;
        if (e < NRWIN * DIM) {
            int iloc = e / DIM;
            int jp   = e - iloc * DIM;
            int g    = min(min((int)gFs[e], (int)gBs[e]), GCLAMP);
            hsq16[e] = (unsigned short)(g * g + jp * jp);
        }
        e = TPB + tid;
        if (e < NRWIN * DIM) {
            int iloc = e / DIM;
            int jp   = e - iloc * DIM;
            int g    = min(min((int)gFs[e], (int)gBs[e]), GCLAMP);
            hsq16[e] = (unsigned short)(g * g + jp * jp);
        }
    }
    __syncthreads();

    // ---- phase 2 (DPX s16x2): d^2 = min_jp (h[jp] + j0^2 - 2*jp*j0) ----
    const int i0   = q0 / DIM;
    const int j0   = q0 - i0 * DIM;
    const int iloc = i0 - r0;
    int maxd2 = -1;                               // sentinel: not a source pixel
    if (srcbit) {
        const int j0sq = j0 * j0;
        // packed coeff pair (even jp lane = low, odd jp lane = high)
        unsigned int cpair = (unsigned int)((j0sq & 0xFFFF)
                           | (((j0sq - 2 * j0) & 0xFFFF) << 16));
        const int stp = (-4 * j0) & 0xFFFF;
        const unsigned int cstep = (unsigned int)(stp | (stp << 16));
        unsigned int m = 0x7FFF7FFFu;             // +max s16 both lanes
        const uint4* hrow = (const uint4*)(hsq16 + iloc * DIM);  // warp-uniform -> broadcast
        #pragma unroll
        for (int t = 0; t < 12; ++t) {
            uint4 hh = hrow[t];                   // 8 u16 h-values = 4 (even,odd) pairs
            m = __viaddmin_s16x2(hh.x, cpair, m); cpair = __vadd2(cpair, cstep);
            m = __viaddmin_s16x2(hh.y, cpair, m); cpair = __vadd2(cpair, cstep);
            m = __viaddmin_s16x2(hh.z, cpair, m); cpair = __vadd2(cpair, cstep);
            m = __viaddmin_s16x2(hh.w, cpair, m); cpair = __vadd2(cpair, cstep);
        }
        int lo = (int)(short)(m & 0xFFFF);
        int hi = (int)(short)(m >> 16);
        maxd2 = min(lo, hi);
    }

    // ---- block max-reduce ----
    int v = __reduce_max_sync(0xffffffffu, maxd2);
    if (lane == 0) warpmax[tid >> 5] = v;
    __syncthreads();
    if (tid < 32) {
        int v2 = __reduce_max_sync(0xffffffffu, warpmax[tid]);
        if (tid == 0) {
            g_part[bx] = v2;
            __threadfence();
            int prev = atomicAdd(&g_count, 1);
            lastflag = (prev == NCTA - 1);
        }
    }
    __syncthreads();

    // ---- last CTA finalizes ----
    if (lastflag && tid < 32) {
        float dist = 0.0f;
        if (tid < NBLK16) {
            int vm = -0x7FFFFFFF;
            #pragma unroll
            for (int k = 0; k < NSLICE; ++k)
                vm = max(vm, __ldcg(&g_part[k * NBLK16 + tid]));
            if (vm < 0)            dist = 0.0f;   // empty source set
            else if (vm >= EMPTYT) dist = 1e9f;   // empty target set -> BIG
            else                   dist = sqrtf((float)vm) * (1.0f / (float)DIM);
        }
        float acc = 0.0f;
        #pragma unroll
        for (int ss = 0; ss < NSAMP; ++ss) {
            float d0 = __shfl_sync(0xffffffffu, dist, 2 * ss);
            float d1 = __shfl_sync(0xffffffffu, dist, 2 * ss + 1);
            acc += fmaxf(d0, d1);
        }
        if (tid == 0) {
            out[0]  = acc * (1.0f / (float)NSAMP);
            g_count = 0;   // reset for next graph replay
        }
    }
}

extern "C" void kernel_launch(void* const* d_in, const int* in_sizes, int n_in,
                              void* d_out, int out_size)
{
    const float* predict = (const float*)d_in[0];
    const float* target  = (const float*)d_in[1];
    float* out = (float*)d_out;

    hausdorff_kernel<<<NCTA, TPB>>>(predict, target, out);
}

// round 10
// speedup vs baseline: 1.0752x; 1.0752x over previous
#include <cuda_runtime.h>
#include <cuda_bf16.h>
#include <math.h>

#define HW     9216    // 96*96
#define DIM    96
#define NSAMP  8
#define NBLK16 16
#define NSLICE 9
#define NCTA   (NBLK16 * NSLICE)   // 144 CTAs = single wave
#define TPB    1024
#define INFG   3000    // scan INF marker; INFG+96 still short-safe
#define GCLAMP 150     // clamp for s16 phase-2: 150^2+95^2 = 31525 < 32767
#define EMPTYT 22500   // min possible d^2 when target empty (= GCLAMP^2)
#define NRWIN  12      // 1024 pixels span <= 12 rows
#define HROW   48      // scan segment split row

__device__ int g_max16[NBLK16] = { -1,-1,-1,-1,-1,-1,-1,-1,
                                   -1,-1,-1,-1,-1,-1,-1,-1 };
__device__ int g_count = 0;

__global__ __launch_bounds__(TPB, 1)
void hausdorff_kernel(const float* __restrict__ predict,
                      const float* __restrict__ target,
                      float* __restrict__ out)
{
    const int bx    = blockIdx.x;
    const int blk16 = bx & 15;
    const int slice = bx >> 4;
    const int s     = blk16 >> 1;
    const int dir   = blk16 & 1;
    const int tid   = threadIdx.x;
    const int lane  = tid & 31;

    __shared__ unsigned char tgm[HW];                       // target mask
    __shared__ short gFs[NRWIN * DIM];                      // fwd scan, window
    __shared__ short gBs[NRWIN * DIM];                      // bwd scan, window
    __shared__ short bnF[DIM];                              // true fwd d at row 47
    __shared__ short bnB[DIM];                              // true bwd d at row 48
    __shared__ __align__(16) unsigned short hsq16[NRWIN * DIM]; // clamped g^2+jp^2
    __shared__ int   warpmax[32];

    const int r0 = (slice * TPB) / DIM;                     // first row this CTA needs

    const float* pbase = predict + s * HW;
    const float* tbase = target  + s * HW;
    const float* tsrc  = dir ? pbase : tbase;

    // ---- build target mask, vectorized ((x > 0.5f) == (rint(x) > 0.5) on [0,1)) ----
    const float4* t4 = (const float4*)tsrc;
    #pragma unroll
    for (int v = 0; v < 3; ++v) {
        int idx = v * TPB + tid;
        if (idx < HW / 4) {
            float4 x = t4[idx];
            uchar4 m;
            m.x = x.x > 0.5f;
            m.y = x.y > 0.5f;
            m.z = x.z > 0.5f;
            m.w = x.w > 0.5f;
            ((uchar4*)tgm)[idx] = m;
        }
    }

    // ---- this thread's source-pixel bit (register, no smem) ----
    const int q0 = slice * TPB + tid;
    const bool abit   = pbase[q0] > 0.5f;
    const bool bbit   = tbase[q0] > 0.5f;
    const bool srcbit = dir ? (bbit && !abit) : (abit && !bbit);
    __syncthreads();

    // ---- phase 1: split column scans (48-iter chains, 4 groups x 96 threads) ----
    if (tid < DIM) {                       // fwd, rows 0..47 (exact)
        const int j = tid;
        int d = INFG;
        #pragma unroll
        for (int i = 0; i < HROW; ++i) {
            d = tgm[i * DIM + j] ? 0 : (d + 1);
            if ((unsigned)(i - r0) < NRWIN) gFs[(i - r0) * DIM + j] = (short)d;
        }
        bnF[j] = (short)d;                 // true fwd distance at row 47
    } else if (tid < 2 * DIM) {            // fwd, rows 48..95 (local, fixup later)
        const int j = tid - DIM;
        int d = INFG;
        #pragma unroll
        for (int i = HROW; i < DIM; ++i) {
            d = tgm[i * DIM + j] ? 0 : (d + 1);
            if ((unsigned)(i - r0) < NRWIN) gFs[(i - r0) * DIM + j] = (short)d;
        }
    } else if (tid < 3 * DIM) {            // bwd, rows 95..48 (exact)
        const int j = tid - 2 * DIM;
        int d = INFG;
        #pragma unroll
        for (int i = DIM - 1; i >= HROW; --i) {
            d = tgm[i * DIM + j] ? 0 : (d + 1);
            if ((unsigned)(i - r0) < NRWIN) gBs[(i - r0) * DIM + j] = (short)d;
        }
        bnB[j] = (short)d;                 // true bwd distance at row 48
    } else if (tid < 4 * DIM) {            // bwd, rows 47..0 (local, fixup later)
        const int j = tid - 3 * DIM;
        int d = INFG;
        #pragma unroll
        for (int i = HROW - 1; i >= 0; --i) {
            d = tgm[i * DIM + j] ? 0 : (d + 1);
            if ((unsigned)(i - r0) < NRWIN) gBs[(i - r0) * DIM + j] = (short)d;
        }
    }
    __syncthreads();

    // ---- mini-combine with segment fixup: hsq16 = min(g,GCLAMP)^2 + jp^2 ----
    {
        #pragma unroll
        for (int c = 0; c < 2; ++c) {
            int e = c * TPB + tid;
            if (e < NRWIN * DIM) {
                int iloc = e / DIM;
                int jp   = e - iloc * DIM;
                int i    = r0 + iloc;
                int gf   = gFs[e];
                int gb   = gBs[e];
                if (i >= HROW) gf = min(gf, (int)bnF[jp] + (i - (HROW - 1)));
                else           gb = min(gb, (int)bnB[jp] + (HROW - i));
                int g = min(min(gf, gb), GCLAMP);
                hsq16[e] = (unsigned short)(g * g + jp * jp);
            }
        }
    }
    __syncthreads();

    // ---- phase 2 (DPX s16x2): d^2 = min_jp (h[jp] + j0^2 - 2*jp*j0) ----
    const int i0   = q0 / DIM;
    const int j0   = q0 - i0 * DIM;
    const int iloc = i0 - r0;
    int maxd2 = -1;                               // sentinel: not a source pixel
    if (srcbit) {
        const int j0sq = j0 * j0;
        unsigned int cpair = (unsigned int)((j0sq & 0xFFFF)
                           | (((j0sq - 2 * j0) & 0xFFFF) << 16));
        const int stp = (-4 * j0) & 0xFFFF;
        const unsigned int cstep = (unsigned int)(stp | (stp << 16));
        unsigned int m = 0x7FFF7FFFu;             // +max s16 both lanes
        const uint4* hrow = (const uint4*)(hsq16 + iloc * DIM);  // warp-uniform -> broadcast
        #pragma unroll
        for (int t = 0; t < 12; ++t) {
            uint4 hh = hrow[t];                   // 8 u16 h-values = 4 (even,odd) pairs
            m = __viaddmin_s16x2(hh.x, cpair, m); cpair = __vadd2(cpair, cstep);
            m = __viaddmin_s16x2(hh.y, cpair, m); cpair = __vadd2(cpair, cstep);
            m = __viaddmin_s16x2(hh.z, cpair, m); cpair = __vadd2(cpair, cstep);
            m = __viaddmin_s16x2(hh.w, cpair, m); cpair = __vadd2(cpair, cstep);
        }
        int lo = (int)(short)(m & 0xFFFF);
        int hi = (int)(short)(m >> 16);
        maxd2 = min(lo, hi);
    }

    // ---- block max-reduce; tail confined to warp 0 (no trailing barrier) ----
    int v = __reduce_max_sync(0xffffffffu, maxd2);
    if (lane == 0) warpmax[tid >> 5] = v;
    __syncthreads();
    if (tid < 32) {
        int v2 = __reduce_max_sync(0xffffffffu, warpmax[tid]);
        int prev = 0;
        if (tid == 0) {
            atomicMax(&g_max16[blk16], v2);
            __threadfence();
            prev = atomicAdd(&g_count, 1);
        }
        prev = __shfl_sync(0xffffffffu, prev, 0);

        if (prev == NCTA - 1) {                   // last CTA finalizes
            float dist = 0.0f;
            if (tid < NBLK16) {
                int vm = atomicExch(&g_max16[tid], -1);   // read + reset for replay
                if (vm < 0)            dist = 0.0f;       // empty source set
                else if (vm >= EMPTYT) dist = 1e9f;       // empty target set -> BIG
                else                   dist = sqrtf((float)vm) * (1.0f / (float)DIM);
            }
            float acc = 0.0f;
            #pragma unroll
            for (int ss = 0; ss < NSAMP; ++ss) {
                float d0 = __shfl_sync(0xffffffffu, dist, 2 * ss);
                float d1 = __shfl_sync(0xffffffffu, dist, 2 * ss + 1);
                acc += fmaxf(d0, d1);
            }
            if (tid == 0) {
                out[0]  = acc * (1.0f / (float)NSAMP);
                g_count = 0;                      // reset for next graph replay
            }
        }
    }
}

extern "C" void kernel_launch(void* const* d_in, const int* in_sizes, int n_in,
                              void* d_out, int out_size)
{
    const float* predict = (const float*)d_in[0];
    const float* target  = (const float*)d_in[1];
    float* out = (float*)d_out;

    hausdorff_kernel<<<NCTA, TPB>>>(predict, target, out);
}